// round 1
// baseline (speedup 1.0000x reference)
#include <cuda_runtime.h>
#include <math.h>

// Shapes (fixed for this problem)
#define BB 128
#define SS 1024
#define DD 256
#define AA 256
#define OO 256
#define NROWS (BB*SS)          // 131072 total rows
#define TILE_ROWS 32
#define SPLITS 8               // s-splits for final reduction

// Scratch (static device globals; no allocation)
__device__ float g_vu[NROWS];                  // masked vu
__device__ float g_part[BB * SPLITS * OO];     // partial outputs

// ---------------------------------------------------------------------------
// Kernel 1: per 32-row tile, fused
//   t = x@W + b ; t = t/max(||t||,eps) ; v = tanh(t)
//   vu = (v.u)*mask  -> g_vu
//   vuo = (v@Uo)*mask ; betas = masked softmax over O -> betas_out
// Thread map: 256 threads = 8 warps; warp ty owns rows ty*4..ty*4+3;
// lane tx owns cols {tx, tx+32, ..., tx+224}. Row reductions = warp shuffles.
// ---------------------------------------------------------------------------
__global__ __launch_bounds__(256)
void k_fused(const float* __restrict__ x, const float* __restrict__ mask,
             const float* __restrict__ W, const float* __restrict__ bvec,
             const float* __restrict__ u, const float* __restrict__ Uo,
             float* __restrict__ betas_out)
{
    extern __shared__ float sm[];
    float* xs = sm;               // 32*256   (x tile, later reused as v tile)
    float* ws = sm + 8192;        // 32*256   (W / Uo k-chunk)
    float* bs = sm + 16384;       // 256
    float* us = sm + 16640;       // 256
    float* ms = sm + 16896;       // 32

    const int tid = threadIdx.x;
    const int tx  = tid & 31;
    const int ty  = tid >> 5;
    const int row0 = blockIdx.x * TILE_ROWS;

    // Load x tile (coalesced)
    const float* xg = x + (size_t)row0 * DD;
    #pragma unroll
    for (int i = 0; i < (TILE_ROWS*DD)/256; i++) xs[tid + i*256] = xg[tid + i*256];
    bs[tid] = bvec[tid];
    us[tid] = u[tid];
    if (tid < TILE_ROWS) ms[tid] = mask[row0 + tid];
    __syncthreads();

    float acc[4][8];
    #pragma unroll
    for (int i = 0; i < 4; i++)
        #pragma unroll
        for (int j = 0; j < 8; j++) acc[i][j] = 0.0f;

    // ---- GEMM1: t = x @ W ----
    for (int kc = 0; kc < DD; kc += 32) {
        const float4* wg  = (const float4*)(W + kc * AA);
        float4* wsv = (float4*)ws;
        #pragma unroll
        for (int i = 0; i < 8; i++) wsv[tid + i*256] = wg[tid + i*256];
        __syncthreads();
        #pragma unroll 8
        for (int kk = 0; kk < 32; kk++) {
            float xa[4];
            #pragma unroll
            for (int i = 0; i < 4; i++) xa[i] = xs[(ty*4+i)*DD + kc + kk];
            #pragma unroll
            for (int j = 0; j < 8; j++) {
                float wv = ws[kk*AA + tx + 32*j];
                #pragma unroll
                for (int i = 0; i < 4; i++) acc[i][j] = fmaf(xa[i], wv, acc[i][j]);
            }
        }
        __syncthreads();
    }

    // ---- bias + normalize + tanh + vu ; store v into xs (reuse) ----
    #pragma unroll
    for (int i = 0; i < 4; i++) {
        float ss = 0.0f;
        #pragma unroll
        for (int j = 0; j < 8; j++) {
            acc[i][j] += bs[tx + 32*j];
            ss = fmaf(acc[i][j], acc[i][j], ss);
        }
        #pragma unroll
        for (int off = 16; off; off >>= 1) ss += __shfl_xor_sync(0xffffffffu, ss, off);
        float inv = 1.0f / fmaxf(sqrtf(ss), 1e-12f);
        float dot = 0.0f;
        #pragma unroll
        for (int j = 0; j < 8; j++) {
            float v = tanhf(acc[i][j] * inv);
            acc[i][j] = v;
            dot = fmaf(v, us[tx + 32*j], dot);
        }
        #pragma unroll
        for (int off = 16; off; off >>= 1) dot += __shfl_xor_sync(0xffffffffu, dot, off);
        // write v to shared (xs reuse is safe: all GEMM1 reads completed at last sync)
        #pragma unroll
        for (int j = 0; j < 8; j++) xs[(ty*4+i)*AA + tx + 32*j] = acc[i][j];
        if (tx == 0) g_vu[row0 + ty*4 + i] = dot * ms[ty*4 + i];
    }
    __syncthreads();

    // ---- GEMM2: vuo = v @ Uo ----
    #pragma unroll
    for (int i = 0; i < 4; i++)
        #pragma unroll
        for (int j = 0; j < 8; j++) acc[i][j] = 0.0f;

    for (int kc = 0; kc < AA; kc += 32) {
        const float4* wg  = (const float4*)(Uo + kc * OO);
        float4* wsv = (float4*)ws;
        #pragma unroll
        for (int i = 0; i < 8; i++) wsv[tid + i*256] = wg[tid + i*256];
        __syncthreads();
        #pragma unroll 8
        for (int kk = 0; kk < 32; kk++) {
            float xa[4];
            #pragma unroll
            for (int i = 0; i < 4; i++) xa[i] = xs[(ty*4+i)*AA + kc + kk];
            #pragma unroll
            for (int j = 0; j < 8; j++) {
                float wv = ws[kk*OO + tx + 32*j];
                #pragma unroll
                for (int i = 0; i < 4; i++) acc[i][j] = fmaf(xa[i], wv, acc[i][j]);
            }
        }
        __syncthreads();
    }

    // ---- mask + masked softmax over O -> betas ----
    #pragma unroll
    for (int i = 0; i < 4; i++) {
        float m = ms[ty*4 + i];
        float mx = -3.4e38f;
        #pragma unroll
        for (int j = 0; j < 8; j++) { acc[i][j] *= m; mx = fmaxf(mx, acc[i][j]); }
        #pragma unroll
        for (int off = 16; off; off >>= 1) mx = fmaxf(mx, __shfl_xor_sync(0xffffffffu, mx, off));
        float sum = 0.0f;
        float e[8];
        #pragma unroll
        for (int j = 0; j < 8; j++) { e[j] = __expf(acc[i][j] - mx) * m; sum += e[j]; }
        #pragma unroll
        for (int off = 16; off; off >>= 1) sum += __shfl_xor_sync(0xffffffffu, sum, off);
        float inv = (sum == 0.0f) ? 1.0f : (1.0f / sum);
        float* bo = betas_out + (size_t)(row0 + ty*4 + i) * OO;
        #pragma unroll
        for (int j = 0; j < 8; j++) bo[tx + 32*j] = e[j] * inv;
    }
}

// ---------------------------------------------------------------------------
// Kernel 2: alphas = masked softmax of g_vu over S, per batch
// ---------------------------------------------------------------------------
__global__ __launch_bounds__(1024)
void k_alphas(const float* __restrict__ mask, float* __restrict__ alphas)
{
    __shared__ float redA[32];
    __shared__ float redB[32];
    const int b = blockIdx.x;
    const int s = threadIdx.x;
    const int lane = s & 31, wid = s >> 5;

    float val = g_vu[b*SS + s];           // already masked
    float m   = mask[b*SS + s];

    float wm = val;
    #pragma unroll
    for (int off = 16; off; off >>= 1) wm = fmaxf(wm, __shfl_xor_sync(0xffffffffu, wm, off));
    if (lane == 0) redA[wid] = wm;
    __syncthreads();
    if (wid == 0) {
        float t = redA[lane];
        #pragma unroll
        for (int off = 16; off; off >>= 1) t = fmaxf(t, __shfl_xor_sync(0xffffffffu, t, off));
        if (lane == 0) redA[0] = t;
    }
    __syncthreads();
    float mx = redA[0];

    float e = __expf(val - mx) * m;
    float wsm = e;
    #pragma unroll
    for (int off = 16; off; off >>= 1) wsm += __shfl_xor_sync(0xffffffffu, wsm, off);
    if (lane == 0) redB[wid] = wsm;
    __syncthreads();
    if (wid == 0) {
        float t = redB[lane];
        #pragma unroll
        for (int off = 16; off; off >>= 1) t += __shfl_xor_sync(0xffffffffu, t, off);
        if (lane == 0) redB[0] = t;
    }
    __syncthreads();
    float sum = redB[0];
    float inv = (sum == 0.0f) ? 1.0f : (1.0f / sum);
    alphas[b*SS + s] = e * inv;
}

// ---------------------------------------------------------------------------
// Kernel 3a: partial output over an S-split; skip alpha==0 rows (masked)
// ---------------------------------------------------------------------------
__global__ __launch_bounds__(256)
void k_partial(const float* __restrict__ x, const float* __restrict__ alphas,
               const float* __restrict__ betas)
{
    __shared__ float as[SS / SPLITS];
    const int b = blockIdx.x, sp = blockIdx.y, o = threadIdx.x;
    const int s0 = sp * (SS / SPLITS);
    if (o < SS / SPLITS) as[o] = alphas[b*SS + s0 + o];
    __syncthreads();

    float accv = 0.0f;
    for (int si = 0; si < SS / SPLITS; si++) {
        float a = as[si];
        if (a != 0.0f) {
            size_t base = ((size_t)b * SS + s0 + si) * OO + o;
            accv = fmaf(x[base] * a, betas[base], accv);
        }
    }
    g_part[(b * SPLITS + sp) * OO + o] = accv;
}

// Kernel 3b: deterministic reduce of the SPLITS partials
__global__ __launch_bounds__(256)
void k_reduce(float* __restrict__ out)
{
    const int idx = blockIdx.x * 256 + threadIdx.x;   // [0, B*O)
    const int b = idx >> 8, o = idx & 255;
    float s = 0.0f;
    #pragma unroll
    for (int sp = 0; sp < SPLITS; sp++) s += g_part[(b * SPLITS + sp) * OO + o];
    out[idx] = s;
}

// ---------------------------------------------------------------------------
extern "C" void kernel_launch(void* const* d_in, const int* in_sizes, int n_in,
                              void* d_out, int out_size)
{
    const float* x    = (const float*)d_in[0];   // [B,S,D]
    const float* mask = (const float*)d_in[1];   // [B,S]
    const float* W    = (const float*)d_in[2];   // [D,A]
    const float* bv   = (const float*)d_in[3];   // [A]
    const float* u    = (const float*)d_in[4];   // [A]
    const float* Uo   = (const float*)d_in[5];   // [A,O]

    float* out    = (float*)d_out;               // [B,O]
    float* alphas = out + BB * OO;               // [B,S]
    float* betas  = alphas + BB * SS;            // [B,S,O]

    const int smem = (8192 + 8192 + 256 + 256 + 32) * (int)sizeof(float); // 67712
    cudaFuncSetAttribute(k_fused, cudaFuncAttributeMaxDynamicSharedMemorySize, smem);

    k_fused<<<NROWS / TILE_ROWS, 256, smem>>>(x, mask, W, bv, u, Uo, betas);
    k_alphas<<<BB, 1024>>>(mask, alphas);
    dim3 g3(BB, SPLITS);
    k_partial<<<g3, 256>>>(x, alphas, betas);
    k_reduce<<<(BB * OO) / 256, 256>>>(out);
}

// round 5
// speedup vs baseline: 1.0910x; 1.0910x over previous
#include <cuda_runtime.h>
#include <math.h>
#include <stdint.h>

// Shapes (fixed for this problem)
#define BB 128
#define SS 1024
#define DD 256
#define AA 256
#define OO 256
#define NROWS (BB*SS)
#define TILE_ROWS 32
#define SPLITS 8

// Scratch (static device globals; no allocation)
__device__ float g_vu[NROWS];
__device__ float g_part[BB * SPLITS * OO];
__device__ float g_W2[DD * AA];    // W  pair-interleaved: [k/2][col][2]
__device__ float g_Uo2[AA * OO];   // Uo pair-interleaved: [k/2][col][2]

// packed fp32x2 FMA: d = a*b + d (elementwise on lo/hi)
__device__ __forceinline__ void ffma2(unsigned long long& d,
                                      unsigned long long a,
                                      unsigned long long b) {
    asm("fma.rn.f32x2 %0, %1, %2, %0;" : "+l"(d) : "l"(a), "l"(b));
}

// ---------------------------------------------------------------------------
// Prep: interleave weights by k-pairs. dst[((k>>1)*256 + col)*2 + (k&1)] = src[k*256+col]
// ---------------------------------------------------------------------------
__global__ __launch_bounds__(256)
void k_interleave(const float* __restrict__ W, const float* __restrict__ Uo)
{
    const int idx = blockIdx.x * 256 + threadIdx.x;   // [0, 65536)
    const float* src = blockIdx.y ? Uo : W;
    float* dst = blockIdx.y ? g_Uo2 : g_W2;
    const int k = idx >> 8, col = idx & 255;
    dst[(((k >> 1) << 8) + col) * 2 + (k & 1)] = src[idx];
}

// ---------------------------------------------------------------------------
// Fused kernel: 32-row tile, 256 threads (8 warps).
// warp ty owns rows ty*4..ty*4+3; lane tx owns cols {tx+32j}, j=0..7.
// Accumulators are f32x2 pairs over (even k, odd k).
// ---------------------------------------------------------------------------
__global__ __launch_bounds__(256, 2)
void k_fused(const float* __restrict__ x, const float* __restrict__ mask,
             const float* __restrict__ bvec, const float* __restrict__ u,
             float* __restrict__ betas_out)
{
    extern __shared__ float sm[];
    float* xs = sm;               // 32*256 (x tile; later reused as v tile)
    float* ws = sm + 8192;        // 32*256 (interleaved W/Uo k-chunk)
    float* bs = sm + 16384;       // 256
    float* us = sm + 16640;       // 256
    float* ms = sm + 16896;       // 32

    const int tid = threadIdx.x;
    const int tx  = tid & 31;
    const int ty  = tid >> 5;
    const int row0 = blockIdx.x * TILE_ROWS;

    // Load x tile (coalesced)
    const float* xg = x + (size_t)row0 * DD;
    #pragma unroll
    for (int i = 0; i < (TILE_ROWS*DD)/256; i++) xs[tid + i*256] = xg[tid + i*256];
    bs[tid] = bvec[tid];
    us[tid] = u[tid];
    if (tid < TILE_ROWS) ms[tid] = mask[row0 + tid];
    __syncthreads();

    unsigned long long acc2[4][8];
    #pragma unroll
    for (int i = 0; i < 4; i++)
        #pragma unroll
        for (int j = 0; j < 8; j++) acc2[i][j] = 0ull;

    // ---- GEMM1: t = x @ W  (packed over k pairs) ----
    for (int kc = 0; kc < DD; kc += 32) {
        const float4* wg  = (const float4*)(g_W2 + kc * AA);   // chunk: 16 k-pairs x 512 floats
        float4* wsv = (float4*)ws;
        #pragma unroll
        for (int i = 0; i < 8; i++) wsv[tid + i*256] = wg[tid + i*256];
        __syncthreads();
        #pragma unroll 4
        for (int kk2 = 0; kk2 < 16; kk2++) {
            unsigned long long xa[4];
            #pragma unroll
            for (int i = 0; i < 4; i++)
                xa[i] = *(const unsigned long long*)&xs[(ty*4+i)*DD + kc + 2*kk2];
            #pragma unroll
            for (int j = 0; j < 8; j++) {
                unsigned long long wv =
                    *(const unsigned long long*)&ws[((kk2 << 8) + tx + 32*j) * 2];
                #pragma unroll
                for (int i = 0; i < 4; i++) ffma2(acc2[i][j], xa[i], wv);
            }
        }
        __syncthreads();
    }

    // ---- epilogue1: collapse pairs + bias + normalize + tanh + vu; v -> xs ----
    #pragma unroll
    for (int i = 0; i < 4; i++) {
        float tcol[8];
        float ss = 0.0f;
        #pragma unroll
        for (int j = 0; j < 8; j++) {
            float2 p = *(float2*)&acc2[i][j];
            float t = p.x + p.y + bs[tx + 32*j];
            tcol[j] = t;
            ss = fmaf(t, t, ss);
        }
        #pragma unroll
        for (int off = 16; off; off >>= 1) ss += __shfl_xor_sync(0xffffffffu, ss, off);
        float inv = 1.0f / fmaxf(sqrtf(ss), 1e-12f);
        float dot = 0.0f;
        #pragma unroll
        for (int j = 0; j < 8; j++) {
            float a = tcol[j] * inv;                  // |a| <= 1
            float e = __expf(2.0f * a);
            float v = __fdividef(e - 1.0f, e + 1.0f); // tanh(a)
            tcol[j] = v;
            dot = fmaf(v, us[tx + 32*j], dot);
        }
        #pragma unroll
        for (int off = 16; off; off >>= 1) dot += __shfl_xor_sync(0xffffffffu, dot, off);
        #pragma unroll
        for (int j = 0; j < 8; j++) xs[(ty*4+i)*AA + tx + 32*j] = tcol[j];
        if (tx == 0) g_vu[row0 + ty*4 + i] = dot * ms[ty*4 + i];
    }
    __syncthreads();

    // ---- GEMM2: vuo = v @ Uo ----
    #pragma unroll
    for (int i = 0; i < 4; i++)
        #pragma unroll
        for (int j = 0; j < 8; j++) acc2[i][j] = 0ull;

    for (int kc = 0; kc < AA; kc += 32) {
        const float4* wg  = (const float4*)(g_Uo2 + kc * OO);
        float4* wsv = (float4*)ws;
        #pragma unroll
        for (int i = 0; i < 8; i++) wsv[tid + i*256] = wg[tid + i*256];
        __syncthreads();
        #pragma unroll 4
        for (int kk2 = 0; kk2 < 16; kk2++) {
            unsigned long long xa[4];
            #pragma unroll
            for (int i = 0; i < 4; i++)
                xa[i] = *(const unsigned long long*)&xs[(ty*4+i)*AA + kc + 2*kk2];
            #pragma unroll
            for (int j = 0; j < 8; j++) {
                unsigned long long wv =
                    *(const unsigned long long*)&ws[((kk2 << 8) + tx + 32*j) * 2];
                #pragma unroll
                for (int i = 0; i < 4; i++) ffma2(acc2[i][j], xa[i], wv);
            }
        }
        __syncthreads();
    }

    // ---- epilogue2: mask + masked softmax over O -> betas ----
    #pragma unroll
    for (int i = 0; i < 4; i++) {
        float m = ms[ty*4 + i];
        float val[8];
        float mx = -3.4e38f;
        #pragma unroll
        for (int j = 0; j < 8; j++) {
            float2 p = *(float2*)&acc2[i][j];
            val[j] = (p.x + p.y) * m;
            mx = fmaxf(mx, val[j]);
        }
        #pragma unroll
        for (int off = 16; off; off >>= 1) mx = fmaxf(mx, __shfl_xor_sync(0xffffffffu, mx, off));
        float sum = 0.0f;
        float e[8];
        #pragma unroll
        for (int j = 0; j < 8; j++) { e[j] = __expf(val[j] - mx) * m; sum += e[j]; }
        #pragma unroll
        for (int off = 16; off; off >>= 1) sum += __shfl_xor_sync(0xffffffffu, sum, off);
        float inv = (sum == 0.0f) ? 1.0f : __fdividef(1.0f, sum);
        float* bo = betas_out + (size_t)(row0 + ty*4 + i) * OO;
        #pragma unroll
        for (int j = 0; j < 8; j++) bo[tx + 32*j] = e[j] * inv;
    }
}

// ---------------------------------------------------------------------------
// alphas = masked softmax of g_vu over S, per batch
// ---------------------------------------------------------------------------
__global__ __launch_bounds__(1024)
void k_alphas(const float* __restrict__ mask, float* __restrict__ alphas)
{
    __shared__ float redA[32];
    __shared__ float redB[32];
    const int b = blockIdx.x;
    const int s = threadIdx.x;
    const int lane = s & 31, wid = s >> 5;

    float val = g_vu[b*SS + s];           // already masked
    float m   = mask[b*SS + s];

    float wm = val;
    #pragma unroll
    for (int off = 16; off; off >>= 1) wm = fmaxf(wm, __shfl_xor_sync(0xffffffffu, wm, off));
    if (lane == 0) redA[wid] = wm;
    __syncthreads();
    if (wid == 0) {
        float t = redA[lane];
        #pragma unroll
        for (int off = 16; off; off >>= 1) t = fmaxf(t, __shfl_xor_sync(0xffffffffu, t, off));
        if (lane == 0) redA[0] = t;
    }
    __syncthreads();
    float mx = redA[0];

    float e = __expf(val - mx) * m;
    float wsm = e;
    #pragma unroll
    for (int off = 16; off; off >>= 1) wsm += __shfl_xor_sync(0xffffffffu, wsm, off);
    if (lane == 0) redB[wid] = wsm;
    __syncthreads();
    if (wid == 0) {
        float t = redB[lane];
        #pragma unroll
        for (int off = 16; off; off >>= 1) t += __shfl_xor_sync(0xffffffffu, t, off);
        if (lane == 0) redB[0] = t;
    }
    __syncthreads();
    float sum = redB[0];
    float inv = (sum == 0.0f) ? 1.0f : (1.0f / sum);
    alphas[b*SS + s] = e * inv;
}

// ---------------------------------------------------------------------------
// output partials over S-splits + deterministic reduce
// ---------------------------------------------------------------------------
__global__ __launch_bounds__(256)
void k_partial(const float* __restrict__ x, const float* __restrict__ alphas,
               const float* __restrict__ betas)
{
    __shared__ float as[SS / SPLITS];
    const int b = blockIdx.x, sp = blockIdx.y, o = threadIdx.x;
    const int s0 = sp * (SS / SPLITS);
    if (o < SS / SPLITS) as[o] = alphas[b*SS + s0 + o];
    __syncthreads();

    float accv = 0.0f;
    for (int si = 0; si < SS / SPLITS; si++) {
        float a = as[si];
        if (a != 0.0f) {
            size_t base = ((size_t)b * SS + s0 + si) * OO + o;
            accv = fmaf(x[base] * a, betas[base], accv);
        }
    }
    g_part[(b * SPLITS + sp) * OO + o] = accv;
}

__global__ __launch_bounds__(256)
void k_reduce(float* __restrict__ out)
{
    const int idx = blockIdx.x * 256 + threadIdx.x;
    const int b = idx >> 8, o = idx & 255;
    float s = 0.0f;
    #pragma unroll
    for (int sp = 0; sp < SPLITS; sp++) s += g_part[(b * SPLITS + sp) * OO + o];
    out[idx] = s;
}

// ---------------------------------------------------------------------------
extern "C" void kernel_launch(void* const* d_in, const int* in_sizes, int n_in,
                              void* d_out, int out_size)
{
    const float* x    = (const float*)d_in[0];   // [B,S,D]
    const float* mask = (const float*)d_in[1];   // [B,S]
    const float* W    = (const float*)d_in[2];   // [D,A]
    const float* bv   = (const float*)d_in[3];   // [A]
    const float* u    = (const float*)d_in[4];   // [A]
    const float* Uo   = (const float*)d_in[5];   // [A,O]

    float* out    = (float*)d_out;               // [B,O]
    float* alphas = out + BB * OO;               // [B,S]
    float* betas  = alphas + BB * SS;            // [B,S,O]

    const int smem = (8192 + 8192 + 256 + 256 + 32) * (int)sizeof(float); // 67712
    cudaFuncSetAttribute(k_fused, cudaFuncAttributeMaxDynamicSharedMemorySize, smem);

    dim3 gi(256, 2);
    k_interleave<<<gi, 256>>>(W, Uo);
    k_fused<<<NROWS / TILE_ROWS, 256, smem>>>(x, mask, bv, u, betas);
    k_alphas<<<BB, 1024>>>(mask, alphas);
    dim3 g3(BB, SPLITS);
    k_partial<<<g3, 256>>>(x, alphas, betas);
    k_reduce<<<(BB * OO) / 256, 256>>>(out);
}

// round 7
// speedup vs baseline: 2.2043x; 2.0205x over previous
#include <cuda_runtime.h>
#include <math.h>
#include <stdint.h>

// Shapes (fixed)
#define BB 128
#define SS 1024
#define DD 256
#define AA 256
#define OO 256
#define NROWS (BB*SS)
#define SPLITS 8

#define LDP 264            // padded row stride (floats) for conflict-free frags
#define CHUNK_F (32*LDP)   // 8448 floats per weight chunk buffer

// smem float offsets
#define F_XS   0
#define F_WB   33792
#define F_BS   50688
#define F_US   50944
#define F_MS   51200
#define F_INV  51328
#define SMEM_FLOATS 51456
#define SMEM_BYTES (SMEM_FLOATS*4)   // 205824

// Scratch
__device__ float g_vu[NROWS];
__device__ float g_part[BB * SPLITS * OO];

// ---------------------------------------------------------------------------
__device__ __forceinline__ uint32_t smem_u32(const void* p) {
    uint32_t a;
    asm("{ .reg .u64 t; cvta.to.shared.u64 t, %1; cvt.u32.u64 %0, t; }" : "=r"(a) : "l"(p));
    return a;
}
__device__ __forceinline__ void cp16(uint32_t dst, const float* src) {
    asm volatile("cp.async.cg.shared.global [%0], [%1], 16;" :: "r"(dst), "l"(src));
}
#define CP_COMMIT() asm volatile("cp.async.commit_group;" ::: "memory")
#define CP_WAIT0()  asm volatile("cp.async.wait_group 0;" ::: "memory")
#define CP_WAIT1()  asm volatile("cp.async.wait_group 1;" ::: "memory")

__device__ __forceinline__ float to_tf32(float f) {
    uint32_t u;
    asm("cvt.rna.tf32.f32 %0, %1;" : "=r"(u) : "f"(f));
    return __uint_as_float(u);
}

__device__ __forceinline__ void mma8(float* c, const uint32_t* a, uint32_t b0, uint32_t b1) {
    asm("mma.sync.aligned.m16n8k8.row.col.f32.tf32.tf32.f32 "
        "{%0,%1,%2,%3}, {%4,%5,%6,%7}, {%8,%9}, {%0,%1,%2,%3};"
        : "+f"(c[0]), "+f"(c[1]), "+f"(c[2]), "+f"(c[3])
        : "r"(a[0]), "r"(a[1]), "r"(a[2]), "r"(a[3]), "r"(b0), "r"(b1));
}

// issue one 32x256 weight chunk into a wbuf (padded stride), per-thread slice
__device__ __forceinline__ void issue_chunk(uint32_t wb_u32, const float* gsrc, int tid) {
    #pragma unroll
    for (int i = 0; i < 8; i++) {
        int idx = tid + i * 256;           // 2048 float4s
        int row = idx >> 6, c4 = (idx & 63) * 4;
        cp16(wb_u32 + (uint32_t)(row * LDP + c4) * 4u, gsrc + row * 256 + c4);
    }
    CP_COMMIT();
}

__device__ __forceinline__ void sweep_chunk(float* wb, int tid) {
    #pragma unroll
    for (int i = 0; i < 32; i++) {
        int idx = tid + i * 256;           // 8192 elems
        int row = idx >> 8, col = idx & 255;
        wb[row * LDP + col] = to_tf32(wb[row * LDP + col]);
    }
}

// one 32-k chunk of MMAs: acc += A(xs cols [kbase,kbase+32)) * B(wb)
__device__ __forceinline__ void compute_chunk(float acc[2][16][4], const float* xs,
                                              const float* wb, int kbase,
                                              int wr, int wc, int gid, int tig) {
    #pragma unroll
    for (int ks = 0; ks < 4; ks++) {
        const int k0 = ks * 8;
        uint32_t a[2][4];
        #pragma unroll
        for (int mt = 0; mt < 2; mt++) {
            const float* xr = xs + (wr * 32 + mt * 16 + gid) * LDP + kbase + k0 + tig;
            a[mt][0] = __float_as_uint(xr[0]);
            a[mt][1] = __float_as_uint(xr[8 * LDP]);
            a[mt][2] = __float_as_uint(xr[4]);
            a[mt][3] = __float_as_uint(xr[8 * LDP + 4]);
        }
        #pragma unroll
        for (int nt = 0; nt < 16; nt++) {
            const float* wp = wb + (k0 + tig) * LDP + wc * 128 + nt * 8 + gid;
            uint32_t b0 = __float_as_uint(wp[0]);
            uint32_t b1 = __float_as_uint(wp[4 * LDP]);
            mma8(acc[0][nt], a[0], b0, b1);
            mma8(acc[1][nt], a[1], b0, b1);
        }
    }
}

// write C fragments into xs (padded layout), raw values
__device__ __forceinline__ void store_frags(float acc[2][16][4], float* xs,
                                            int wr, int wc, int gid, int tig) {
    #pragma unroll
    for (int mt = 0; mt < 2; mt++) {
        #pragma unroll
        for (int nt = 0; nt < 16; nt++) {
            int ra = wr * 32 + mt * 16 + gid;
            int cb = wc * 128 + nt * 8 + 2 * tig;
            *(float2*)&xs[ra * LDP + cb]       = make_float2(acc[mt][nt][0], acc[mt][nt][1]);
            *(float2*)&xs[(ra + 8) * LDP + cb] = make_float2(acc[mt][nt][2], acc[mt][nt][3]);
        }
    }
}

// full GEMM over 8 chunks with double-buffered cp.async (prologue for chunks 0,1
// must already be issued; buf0 must already be swept)
__device__ __forceinline__ void gemm_loop(float acc[2][16][4], const float* __restrict__ gW,
                                          const float* xs, float* wb, uint32_t wb_u32,
                                          int wr, int wc, int gid, int tig, int tid) {
    for (int kc = 0; kc < 8; kc++) {
        const int cur = kc & 1;
        compute_chunk(acc, xs, wb + cur * CHUNK_F, kc * 32, wr, wc, gid, tig);
        __syncthreads();
        if (kc + 2 < 8)
            issue_chunk(wb_u32 + (uint32_t)cur * CHUNK_F * 4u, gW + (kc + 2) * 32 * 256, tid);
        if (kc + 1 < 8) {
            if (kc + 2 < 8) CP_WAIT1(); else CP_WAIT0();
            __syncthreads();
            sweep_chunk(wb + ((kc + 1) & 1) * CHUNK_F, tid);
            __syncthreads();
        }
    }
}

// ---------------------------------------------------------------------------
__global__ void __launch_bounds__(256, 1)
k_fused(const float* __restrict__ x, const float* __restrict__ mask,
        const float* __restrict__ W, const float* __restrict__ bvec,
        const float* __restrict__ u, const float* __restrict__ Uo,
        float* __restrict__ betas_out)
{
    extern __shared__ float sm[];
    float* xs   = sm + F_XS;
    float* wb   = sm + F_WB;
    float* bs   = sm + F_BS;
    float* us   = sm + F_US;
    float* ms   = sm + F_MS;
    float* invp = sm + F_INV;

    const uint32_t smb    = smem_u32(sm);
    const uint32_t xs_u32 = smb + F_XS * 4;
    const uint32_t wb_u32 = smb + F_WB * 4;

    const int tid  = threadIdx.x;
    const int lane = tid & 31;
    const int wid  = tid >> 5;
    const int wr   = wid >> 1;       // 0..3 (32-row stripe)
    const int wc   = wid & 1;        // 0..1 (128-col half)
    const int gid  = lane >> 2;
    const int tig  = lane & 3;
    const int row0 = blockIdx.x * 128;

    // headers
    bs[tid] = bvec[tid];
    us[tid] = u[tid];
    if (tid < 128) ms[tid] = mask[row0 + tid];

    // prologue: x tile + W chunks 0,1
    {
        const float* xg = x + (size_t)row0 * DD;
        #pragma unroll
        for (int i = 0; i < 32; i++) {
            int idx = tid + i * 256;       // 8192 float4s
            int row = idx >> 6, c4 = (idx & 63) * 4;
            cp16(xs_u32 + (uint32_t)(row * LDP + c4) * 4u, xg + row * 256 + c4);
        }
        CP_COMMIT();
        issue_chunk(wb_u32, W, tid);
        issue_chunk(wb_u32 + CHUNK_F * 4u, W + 32 * 256, tid);
    }
    CP_WAIT1();                            // xs + chunk0 landed
    __syncthreads();
    // tf32-round xs and chunk0
    #pragma unroll
    for (int i = 0; i < 128; i++) {
        int idx = tid + i * 256;           // 32768 elems
        int row = idx >> 8, col = idx & 255;
        xs[row * LDP + col] = to_tf32(xs[row * LDP + col]);
    }
    sweep_chunk(wb, tid);
    __syncthreads();

    float acc[2][16][4];

    // ---------------- GEMM1: t = x @ W ----------------
    #pragma unroll
    for (int mt = 0; mt < 2; mt++)
        #pragma unroll
        for (int nt = 0; nt < 16; nt++)
            #pragma unroll
            for (int c = 0; c < 4; c++) acc[mt][nt][c] = 0.0f;

    gemm_loop(acc, W, xs, wb, wb_u32, wr, wc, gid, tig, tid);

    store_frags(acc, xs, wr, wc, gid, tig);
    __syncthreads();

    // prefetch Uo chunks 0,1 during epilogue1
    issue_chunk(wb_u32, Uo, tid);
    issue_chunk(wb_u32 + CHUNK_F * 4u, Uo + 32 * 256, tid);

    // ---------------- epilogue1: bias + normalize + tanh + vu; v->xs (tf32)
    {
        const int r = tid >> 1, h = tid & 1;
        float* rowp = xs + r * LDP + h * 128;
        const float* bp = bs + h * 128;
        const float* up = us + h * 128;
        float ssum = 0.0f;
        #pragma unroll 8
        for (int c = 0; c < 128; c++) {
            float t = rowp[c] + bp[c];
            rowp[c] = t;
            ssum = fmaf(t, t, ssum);
        }
        ssum += __shfl_xor_sync(0xffffffffu, ssum, 1);
        const float invn = 1.0f / fmaxf(sqrtf(ssum), 1e-12f);
        float vu = 0.0f;
        #pragma unroll 8
        for (int c = 0; c < 128; c++) {
            float a = rowp[c] * invn;                 // |a| <= 1
            float e = __expf(2.0f * a);
            float v = __fdividef(e - 1.0f, e + 1.0f); // tanh
            vu = fmaf(v, up[c], vu);
            rowp[c] = to_tf32(v);
        }
        vu += __shfl_xor_sync(0xffffffffu, vu, 1);
        if (h == 0) g_vu[row0 + r] = vu * ms[r];
    }
    CP_WAIT1();
    __syncthreads();
    sweep_chunk(wb, tid);
    __syncthreads();

    // ---------------- GEMM2: vuo = v @ Uo ----------------
    #pragma unroll
    for (int mt = 0; mt < 2; mt++)
        #pragma unroll
        for (int nt = 0; nt < 16; nt++)
            #pragma unroll
            for (int c = 0; c < 4; c++) acc[mt][nt][c] = 0.0f;

    gemm_loop(acc, Uo, xs, wb, wb_u32, wr, wc, gid, tig, tid);

    store_frags(acc, xs, wr, wc, gid, tig);
    __syncthreads();

    // ---------------- epilogue2: mask + softmax over O -> betas ----------------
    {
        const int r = tid >> 1, h = tid & 1;
        float* rowp = xs + r * LDP + h * 128;
        const float m = ms[r];
        float mx = -3.4e38f;
        #pragma unroll 8
        for (int c = 0; c < 128; c++) {
            float v = rowp[c] * m;
            rowp[c] = v;
            mx = fmaxf(mx, v);
        }
        mx = fmaxf(mx, __shfl_xor_sync(0xffffffffu, mx, 1));
        float sum = 0.0f;
        #pragma unroll 8
        for (int c = 0; c < 128; c++) {
            float e = __expf(rowp[c] - mx) * m;
            rowp[c] = e;
            sum += e;
        }
        sum += __shfl_xor_sync(0xffffffffu, sum, 1);
        if (h == 0) invp[r] = (sum == 0.0f) ? 1.0f : __fdividef(1.0f, sum);
    }
    __syncthreads();
    {
        float* bo = betas_out + (size_t)row0 * OO;
        #pragma unroll
        for (int i = 0; i < 32; i++) {
            int idx = tid + i * 256;       // 8192 float4s
            int row = idx >> 6, c4 = (idx & 63) * 4;
            float iv = invp[row];
            const float* sp = xs + row * LDP + c4;
            float4 v = make_float4(sp[0] * iv, sp[1] * iv, sp[2] * iv, sp[3] * iv);
            *(float4*)(bo + row * 256 + c4) = v;
        }
    }
}

// ---------------------------------------------------------------------------
// alphas = masked softmax of g_vu over S, per batch
// ---------------------------------------------------------------------------
__global__ __launch_bounds__(1024)
void k_alphas(const float* __restrict__ mask, float* __restrict__ alphas)
{
    __shared__ float redA[32];
    __shared__ float redB[32];
    const int b = blockIdx.x;
    const int s = threadIdx.x;
    const int lane = s & 31, wid = s >> 5;

    float val = g_vu[b*SS + s];
    float m   = mask[b*SS + s];

    float wm = val;
    #pragma unroll
    for (int off = 16; off; off >>= 1) wm = fmaxf(wm, __shfl_xor_sync(0xffffffffu, wm, off));
    if (lane == 0) redA[wid] = wm;
    __syncthreads();
    if (wid == 0) {
        float t = redA[lane];
        #pragma unroll
        for (int off = 16; off; off >>= 1) t = fmaxf(t, __shfl_xor_sync(0xffffffffu, t, off));
        if (lane == 0) redA[0] = t;
    }
    __syncthreads();
    float mx = redA[0];

    float e = __expf(val - mx) * m;
    float wsm = e;
    #pragma unroll
    for (int off = 16; off; off >>= 1) wsm += __shfl_xor_sync(0xffffffffu, wsm, off);
    if (lane == 0) redB[wid] = wsm;
    __syncthreads();
    if (wid == 0) {
        float t = redB[lane];
        #pragma unroll
        for (int off = 16; off; off >>= 1) t += __shfl_xor_sync(0xffffffffu, t, off);
        if (lane == 0) redB[0] = t;
    }
    __syncthreads();
    float sum = redB[0];
    float inv = (sum == 0.0f) ? 1.0f : (1.0f / sum);
    alphas[b*SS + s] = e * inv;
}

// ---------------------------------------------------------------------------
// output partials over S-splits + deterministic reduce
// ---------------------------------------------------------------------------
__global__ __launch_bounds__(256)
void k_partial(const float* __restrict__ x, const float* __restrict__ alphas,
               const float* __restrict__ betas)
{
    __shared__ float as[SS / SPLITS];
    const int b = blockIdx.x, sp = blockIdx.y, o = threadIdx.x;
    const int s0 = sp * (SS / SPLITS);
    if (o < SS / SPLITS) as[o] = alphas[b*SS + s0 + o];
    __syncthreads();

    float accv = 0.0f;
    for (int si = 0; si < SS / SPLITS; si++) {
        float a = as[si];
        if (a != 0.0f) {
            size_t base = ((size_t)b * SS + s0 + si) * OO + o;
            accv = fmaf(x[base] * a, betas[base], accv);
        }
    }
    g_part[(b * SPLITS + sp) * OO + o] = accv;
}

__global__ __launch_bounds__(256)
void k_reduce(float* __restrict__ out)
{
    const int idx = blockIdx.x * 256 + threadIdx.x;
    const int b = idx >> 8, o = idx & 255;
    float s = 0.0f;
    #pragma unroll
    for (int sp = 0; sp < SPLITS; sp++) s += g_part[(b * SPLITS + sp) * OO + o];
    out[idx] = s;
}

// ---------------------------------------------------------------------------
extern "C" void kernel_launch(void* const* d_in, const int* in_sizes, int n_in,
                              void* d_out, int out_size)
{
    const float* x    = (const float*)d_in[0];   // [B,S,D]
    const float* mask = (const float*)d_in[1];   // [B,S]
    const float* W    = (const float*)d_in[2];   // [D,A]
    const float* bv   = (const float*)d_in[3];   // [A]
    const float* u    = (const float*)d_in[4];   // [A]
    const float* Uo   = (const float*)d_in[5];   // [A,O]

    float* out    = (float*)d_out;               // [B,O]
    float* alphas = out + BB * OO;               // [B,S]
    float* betas  = alphas + BB * SS;            // [B,S,O]

    cudaFuncSetAttribute(k_fused, cudaFuncAttributeMaxDynamicSharedMemorySize, SMEM_BYTES);

    k_fused<<<NROWS / 128, 256, SMEM_BYTES>>>(x, mask, W, bv, u, Uo, betas);
    k_alphas<<<BB, 1024>>>(mask, alphas);
    dim3 g3(BB, SPLITS);
    k_partial<<<g3, 256>>>(x, alphas, betas);
    k_reduce<<<(BB * OO) / 256, 256>>>(out);
}

// round 8
// speedup vs baseline: 2.3873x; 1.0830x over previous
#include <cuda_runtime.h>
#include <math.h>
#include <stdint.h>

// Shapes (fixed)
#define BB 128
#define SS 1024
#define DD 256
#define AA 256
#define OO 256
#define NROWS (BB*SS)
#define SPLITS 16

#define LDP 264            // padded row stride (floats) for conflict-free frags
#define CHUNK_F (32*LDP)   // 8448 floats per weight chunk buffer

// smem float offsets
#define F_XS   0
#define F_WB   33792
#define F_BS   50688
#define F_US   50944
#define F_MS   51200
#define F_INV  51328
#define SMEM_FLOATS 51456
#define SMEM_BYTES (SMEM_FLOATS*4)   // 205824

// Scratch
__device__ float g_vu[NROWS];
__device__ float g_part[BB * SPLITS * OO];

// ---------------------------------------------------------------------------
__device__ __forceinline__ uint32_t smem_u32(const void* p) {
    uint32_t a;
    asm("{ .reg .u64 t; cvta.to.shared.u64 t, %1; cvt.u32.u64 %0, t; }" : "=r"(a) : "l"(p));
    return a;
}
__device__ __forceinline__ void cp16(uint32_t dst, const float* src) {
    asm volatile("cp.async.cg.shared.global [%0], [%1], 16;" :: "r"(dst), "l"(src));
}
#define CP_COMMIT() asm volatile("cp.async.commit_group;" ::: "memory")
#define CP_WAIT0()  asm volatile("cp.async.wait_group 0;" ::: "memory")
#define CP_WAIT1()  asm volatile("cp.async.wait_group 1;" ::: "memory")

__device__ __forceinline__ void mma8(float* c, const uint32_t* a, uint32_t b0, uint32_t b1) {
    asm("mma.sync.aligned.m16n8k8.row.col.f32.tf32.tf32.f32 "
        "{%0,%1,%2,%3}, {%4,%5,%6,%7}, {%8,%9}, {%0,%1,%2,%3};"
        : "+f"(c[0]), "+f"(c[1]), "+f"(c[2]), "+f"(c[3])
        : "r"(a[0]), "r"(a[1]), "r"(a[2]), "r"(a[3]), "r"(b0), "r"(b1));
}

// issue one 32x256 weight chunk into a wbuf (padded stride), per-thread slice
__device__ __forceinline__ void issue_chunk(uint32_t wb_u32, const float* gsrc, int tid) {
    #pragma unroll
    for (int i = 0; i < 8; i++) {
        int idx = tid + i * 256;           // 2048 float4s
        int row = idx >> 6, c4 = (idx & 63) * 4;
        cp16(wb_u32 + (uint32_t)(row * LDP + c4) * 4u, gsrc + row * 256 + c4);
    }
    CP_COMMIT();
}

// one 32-k chunk of MMAs: acc += A(xs cols [kbase,kbase+32)) * B(wb)
// fp32 operands fed raw; HW truncates to tf32.
__device__ __forceinline__ void compute_chunk(float acc[2][16][4], const float* xs,
                                              const float* wb, int kbase,
                                              int wr, int wc, int gid, int tig) {
    #pragma unroll
    for (int ks = 0; ks < 4; ks++) {
        const int k0 = ks * 8;
        uint32_t a[2][4];
        #pragma unroll
        for (int mt = 0; mt < 2; mt++) {
            const float* xr = xs + (wr * 32 + mt * 16 + gid) * LDP + kbase + k0 + tig;
            a[mt][0] = __float_as_uint(xr[0]);
            a[mt][1] = __float_as_uint(xr[8 * LDP]);
            a[mt][2] = __float_as_uint(xr[4]);
            a[mt][3] = __float_as_uint(xr[8 * LDP + 4]);
        }
        #pragma unroll
        for (int nt = 0; nt < 16; nt++) {
            const float* wp = wb + (k0 + tig) * LDP + wc * 128 + nt * 8 + gid;
            uint32_t b0 = __float_as_uint(wp[0]);
            uint32_t b1 = __float_as_uint(wp[4 * LDP]);
            mma8(acc[0][nt], a[0], b0, b1);
            mma8(acc[1][nt], a[1], b0, b1);
        }
    }
}

// write C fragments into xs (padded layout), raw values
__device__ __forceinline__ void store_frags(float acc[2][16][4], float* xs,
                                            int wr, int wc, int gid, int tig) {
    #pragma unroll
    for (int mt = 0; mt < 2; mt++) {
        #pragma unroll
        for (int nt = 0; nt < 16; nt++) {
            int ra = wr * 32 + mt * 16 + gid;
            int cb = wc * 128 + nt * 8 + 2 * tig;
            *(float2*)&xs[ra * LDP + cb]       = make_float2(acc[mt][nt][0], acc[mt][nt][1]);
            *(float2*)&xs[(ra + 8) * LDP + cb] = make_float2(acc[mt][nt][2], acc[mt][nt][3]);
        }
    }
}

// full GEMM over 8 chunks, double-buffered cp.async (chunks 0,1 pre-issued;
// chunk0 must be visible: caller does CP_WAIT1 + __syncthreads before)
__device__ __forceinline__ void gemm_loop(float acc[2][16][4], const float* __restrict__ gW,
                                          const float* xs, float* wb, uint32_t wb_u32,
                                          int wr, int wc, int gid, int tig, int tid) {
    for (int kc = 0; kc < 8; kc++) {
        const int cur = kc & 1;
        compute_chunk(acc, xs, wb + cur * CHUNK_F, kc * 32, wr, wc, gid, tig);
        __syncthreads();                   // all warps done reading cur buffer
        if (kc + 2 < 8)
            issue_chunk(wb_u32 + (uint32_t)cur * CHUNK_F * 4u, gW + (kc + 2) * 32 * 256, tid);
        if (kc + 1 < 8) {
            if (kc + 2 < 8) CP_WAIT1(); else CP_WAIT0();
            __syncthreads();               // chunk kc+1 visible to all warps
        }
    }
}

// ---------------------------------------------------------------------------
__global__ void __launch_bounds__(256, 1)
k_fused(const float* __restrict__ x, const float* __restrict__ mask,
        const float* __restrict__ W, const float* __restrict__ bvec,
        const float* __restrict__ u, const float* __restrict__ Uo,
        float* __restrict__ betas_out)
{
    extern __shared__ float sm[];
    float* xs   = sm + F_XS;
    float* wb   = sm + F_WB;
    float* bs   = sm + F_BS;
    float* us   = sm + F_US;
    float* ms   = sm + F_MS;
    float* invp = sm + F_INV;

    const uint32_t smb    = smem_u32(sm);
    const uint32_t xs_u32 = smb + F_XS * 4;
    const uint32_t wb_u32 = smb + F_WB * 4;

    const int tid  = threadIdx.x;
    const int lane = tid & 31;
    const int wid  = tid >> 5;
    const int wr   = wid >> 1;       // 0..3 (32-row stripe)
    const int wc   = wid & 1;        // 0..1 (128-col half)
    const int gid  = lane >> 2;
    const int tig  = lane & 3;
    const int row0 = blockIdx.x * 128;

    // headers
    bs[tid] = bvec[tid];
    us[tid] = u[tid];
    if (tid < 128) ms[tid] = mask[row0 + tid];

    // prologue: x tile + W chunks 0,1 (three commit groups)
    {
        const float* xg = x + (size_t)row0 * DD;
        #pragma unroll
        for (int i = 0; i < 32; i++) {
            int idx = tid + i * 256;       // 8192 float4s
            int row = idx >> 6, c4 = (idx & 63) * 4;
            cp16(xs_u32 + (uint32_t)(row * LDP + c4) * 4u, xg + row * 256 + c4);
        }
        CP_COMMIT();
        issue_chunk(wb_u32, W, tid);
        issue_chunk(wb_u32 + CHUNK_F * 4u, W + 32 * 256, tid);
    }
    CP_WAIT1();                            // xs + chunk0 landed
    __syncthreads();

    float acc[2][16][4];

    // ---------------- GEMM1: t = x @ W ----------------
    #pragma unroll
    for (int mt = 0; mt < 2; mt++)
        #pragma unroll
        for (int nt = 0; nt < 16; nt++)
            #pragma unroll
            for (int c = 0; c < 4; c++) acc[mt][nt][c] = 0.0f;

    gemm_loop(acc, W, xs, wb, wb_u32, wr, wc, gid, tig, tid);

    store_frags(acc, xs, wr, wc, gid, tig);
    __syncthreads();

    // prefetch Uo chunks 0,1 during epilogue1
    issue_chunk(wb_u32, Uo, tid);
    issue_chunk(wb_u32 + CHUNK_F * 4u, Uo + 32 * 256, tid);

    // ---------------- epilogue1: bias + normalize + tanh + vu; v -> xs ----
    {
        const int r = tid >> 1, h = tid & 1;
        float* rowp = xs + r * LDP + h * 128;
        const float* bp = bs + h * 128;
        const float* up = us + h * 128;
        float ssum = 0.0f;
        #pragma unroll 8
        for (int c = 0; c < 128; c++) {
            float t = rowp[c] + bp[c];
            rowp[c] = t;
            ssum = fmaf(t, t, ssum);
        }
        ssum += __shfl_xor_sync(0xffffffffu, ssum, 1);
        const float invn = 1.0f / fmaxf(sqrtf(ssum), 1e-12f);
        float vu = 0.0f;
        #pragma unroll 8
        for (int c = 0; c < 128; c++) {
            float a = rowp[c] * invn;                 // |a| <= 1
            float e = __expf(2.0f * a);
            float v = __fdividef(e - 1.0f, e + 1.0f); // tanh
            vu = fmaf(v, up[c], vu);
            rowp[c] = v;
        }
        vu += __shfl_xor_sync(0xffffffffu, vu, 1);
        if (h == 0) g_vu[row0 + r] = vu * ms[r];
    }
    CP_WAIT1();                            // Uo chunk0 landed
    __syncthreads();

    // ---------------- GEMM2: vuo = v @ Uo ----------------
    #pragma unroll
    for (int mt = 0; mt < 2; mt++)
        #pragma unroll
        for (int nt = 0; nt < 16; nt++)
            #pragma unroll
            for (int c = 0; c < 4; c++) acc[mt][nt][c] = 0.0f;

    gemm_loop(acc, Uo, xs, wb, wb_u32, wr, wc, gid, tig, tid);

    store_frags(acc, xs, wr, wc, gid, tig);
    __syncthreads();

    // ---------------- epilogue2: mask + softmax over O -> betas ----------------
    {
        const int r = tid >> 1, h = tid & 1;
        float* rowp = xs + r * LDP + h * 128;
        const float m = ms[r];
        float mx = -3.4e38f;
        #pragma unroll 8
        for (int c = 0; c < 128; c++) {
            float v = rowp[c] * m;
            rowp[c] = v;
            mx = fmaxf(mx, v);
        }
        mx = fmaxf(mx, __shfl_xor_sync(0xffffffffu, mx, 1));
        float sum = 0.0f;
        #pragma unroll 8
        for (int c = 0; c < 128; c++) {
            float e = __expf(rowp[c] - mx) * m;
            rowp[c] = e;
            sum += e;
        }
        sum += __shfl_xor_sync(0xffffffffu, sum, 1);
        if (h == 0) invp[r] = (sum == 0.0f) ? 1.0f : __fdividef(1.0f, sum);
    }
    __syncthreads();
    {
        float* bo = betas_out + (size_t)row0 * OO;
        #pragma unroll
        for (int i = 0; i < 32; i++) {
            int idx = tid + i * 256;       // 8192 float4s
            int row = idx >> 6, c4 = (idx & 63) * 4;
            float iv = invp[row];
            const float* sp = xs + row * LDP + c4;
            float4 v = make_float4(sp[0] * iv, sp[1] * iv, sp[2] * iv, sp[3] * iv);
            *(float4*)(bo + row * 256 + c4) = v;
        }
    }
}

// ---------------------------------------------------------------------------
// alphas = masked softmax of g_vu over S, per batch
// ---------------------------------------------------------------------------
__global__ __launch_bounds__(1024)
void k_alphas(const float* __restrict__ mask, float* __restrict__ alphas)
{
    __shared__ float redA[32];
    __shared__ float redB[32];
    const int b = blockIdx.x;
    const int s = threadIdx.x;
    const int lane = s & 31, wid = s >> 5;

    float val = g_vu[b*SS + s];
    float m   = mask[b*SS + s];

    float wm = val;
    #pragma unroll
    for (int off = 16; off; off >>= 1) wm = fmaxf(wm, __shfl_xor_sync(0xffffffffu, wm, off));
    if (lane == 0) redA[wid] = wm;
    __syncthreads();
    if (wid == 0) {
        float t = redA[lane];
        #pragma unroll
        for (int off = 16; off; off >>= 1) t = fmaxf(t, __shfl_xor_sync(0xffffffffu, t, off));
        if (lane == 0) redA[0] = t;
    }
    __syncthreads();
    float mx = redA[0];

    float e = __expf(val - mx) * m;
    float wsm = e;
    #pragma unroll
    for (int off = 16; off; off >>= 1) wsm += __shfl_xor_sync(0xffffffffu, wsm, off);
    if (lane == 0) redB[wid] = wsm;
    __syncthreads();
    if (wid == 0) {
        float t = redB[lane];
        #pragma unroll
        for (int off = 16; off; off >>= 1) t += __shfl_xor_sync(0xffffffffu, t, off);
        if (lane == 0) redB[0] = t;
    }
    __syncthreads();
    float sum = redB[0];
    float inv = (sum == 0.0f) ? 1.0f : (1.0f / sum);
    alphas[b*SS + s] = e * inv;
}

// ---------------------------------------------------------------------------
// output partials over 64-row S-splits, float4 per thread, smem tree over 4 subgroups
// ---------------------------------------------------------------------------
__global__ __launch_bounds__(256)
void k_partial(const float* __restrict__ x, const float* __restrict__ alphas,
               const float* __restrict__ betas)
{
    __shared__ float as[64];
    __shared__ float4 red[4][64];
    const int b = blockIdx.x, sp = blockIdx.y;
    const int tid = threadIdx.x;
    const int o4 = tid & 63, sq = tid >> 6;
    const int s0 = sp * 64;

    if (tid < 64) as[tid] = alphas[b*SS + s0 + tid];
    __syncthreads();

    float4 acc = make_float4(0.f, 0.f, 0.f, 0.f);
    #pragma unroll 4
    for (int si = sq; si < 64; si += 4) {
        float a = as[si];
        if (a != 0.0f) {
            size_t base = ((size_t)b * SS + s0 + si) * OO + o4 * 4;
            float4 xv = *(const float4*)(x + base);
            float4 bv = *(const float4*)(betas + base);
            acc.x = fmaf(xv.x * a, bv.x, acc.x);
            acc.y = fmaf(xv.y * a, bv.y, acc.y);
            acc.z = fmaf(xv.z * a, bv.z, acc.z);
            acc.w = fmaf(xv.w * a, bv.w, acc.w);
        }
    }
    red[sq][o4] = acc;
    __syncthreads();
    if (tid < 64) {
        float4 r0 = red[0][tid], r1 = red[1][tid], r2 = red[2][tid], r3 = red[3][tid];
        float4 s = make_float4(r0.x + r1.x + r2.x + r3.x,
                               r0.y + r1.y + r2.y + r3.y,
                               r0.z + r1.z + r2.z + r3.z,
                               r0.w + r1.w + r2.w + r3.w);
        *(float4*)&g_part[((size_t)b * SPLITS + sp) * OO + tid * 4] = s;
    }
}

__global__ __launch_bounds__(256)
void k_reduce(float* __restrict__ out)
{
    const int idx = blockIdx.x * 256 + threadIdx.x;
    const int b = idx >> 8, o = idx & 255;
    float s = 0.0f;
    #pragma unroll
    for (int sp = 0; sp < SPLITS; sp++) s += g_part[((size_t)b * SPLITS + sp) * OO + o];
    out[idx] = s;
}

// ---------------------------------------------------------------------------
extern "C" void kernel_launch(void* const* d_in, const int* in_sizes, int n_in,
                              void* d_out, int out_size)
{
    const float* x    = (const float*)d_in[0];   // [B,S,D]
    const float* mask = (const float*)d_in[1];   // [B,S]
    const float* W    = (const float*)d_in[2];   // [D,A]
    const float* bv   = (const float*)d_in[3];   // [A]
    const float* u    = (const float*)d_in[4];   // [A]
    const float* Uo   = (const float*)d_in[5];   // [A,O]

    float* out    = (float*)d_out;               // [B,O]
    float* alphas = out + BB * OO;               // [B,S]
    float* betas  = alphas + BB * SS;            // [B,S,O]

    cudaFuncSetAttribute(k_fused, cudaFuncAttributeMaxDynamicSharedMemorySize, SMEM_BYTES);

    k_fused<<<NROWS / 128, 256, SMEM_BYTES>>>(x, mask, W, bv, u, Uo, betas);
    k_alphas<<<BB, 1024>>>(mask, alphas);
    dim3 g3(BB, SPLITS);
    k_partial<<<g3, 256>>>(x, alphas, betas);
    k_reduce<<<(BB * OO) / 256, 256>>>(out);
}